// round 14
// baseline (speedup 1.0000x reference)
#include <cuda_runtime.h>
#include <cuda_fp16.h>
#include <cstdint>

#define NN 50000
#define EMAX 800000
#define EPS 1e-5f
#define CHUNK 12544          // 98 * 128
#define NCHUNK 4
#define NSCAN 196

__device__ __forceinline__ void cpasync16(uint32_t dst, const void* src) {
    asm volatile("cp.async.cg.shared.global [%0], [%1], 16;" :: "r"(dst), "l"(src));
}
__device__ __forceinline__ void cpasync16z(uint32_t dst, const void* src, int size) {
    asm volatile("cp.async.cg.shared.global [%0], [%1], 16, %2;" :: "r"(dst), "l"(src), "r"(size));
}
__device__ __forceinline__ void cpcommit() { asm volatile("cp.async.commit_group;" ::: "memory"); }
__device__ __forceinline__ void cpwait0() { asm volatile("cp.async.wait_group 0;" ::: "memory"); }
__device__ __forceinline__ void cpwait1() { asm volatile("cp.async.wait_group 1;" ::: "memory"); }
__device__ __forceinline__ void cpwait2() { asm volatile("cp.async.wait_group 2;" ::: "memory"); }

// ======================= scratch =======================
__device__ __half g_Xh[NN * 128];
__device__ __half g_h1h[NN * 256];
__device__ __half g_h2h[NN * 256];
__device__ __half g_Mh[NN * 256];
__device__ __align__(16) __half g_Bf[256 * 256 + 2 * 256 * 512];
__device__ int g_counts[NN];
__device__ int g_offsets[NN + 1];
__device__ int g_cursor[NN];
__device__ int g_esrc[EMAX];
__device__ int g_bsum[NSCAN];
__device__ int g_flag[NSCAN];

// ======================= CSR build =======================
__global__ void zero_counts_kernel() {
    int i = blockIdx.x * blockDim.x + threadIdx.x;
    if (i < NN) g_counts[i] = 0;
    if (i < NSCAN) g_flag[i] = 0;
}
__global__ void hist_kernel(const int* __restrict__ dst, int E) {
    int q = blockIdx.x * blockDim.x + threadIdx.x;
    int e = q * 4;
    if (e + 4 <= E) {
        int4 d = *(const int4*)(dst + e);
        atomicAdd(&g_counts[d.x], 1);
        atomicAdd(&g_counts[d.y], 1);
        atomicAdd(&g_counts[d.z], 1);
        atomicAdd(&g_counts[d.w], 1);
    } else {
        for (int k = e; k < E; k++) atomicAdd(&g_counts[dst[k]], 1);
    }
}
__global__ void scan_fused_kernel() {
    __shared__ int s[256];
    __shared__ int sp[256];
    int tid = threadIdx.x;
    int i = blockIdx.x * 256 + tid;
    int v = (i < NN) ? g_counts[i] : 0;
    s[tid] = v;
    __syncthreads();
    #pragma unroll
    for (int off = 1; off < 256; off <<= 1) {
        int t = (tid >= off) ? s[tid - off] : 0;
        __syncthreads();
        s[tid] += t;
        __syncthreads();
    }
    if (tid == 255) {
        g_bsum[blockIdx.x] = s[255];
        __threadfence();
        atomicExch(&g_flag[blockIdx.x], 1);
    }
    int pre = 0;
    for (int b = tid; b < blockIdx.x; b += 256) {
        while (atomicAdd(&g_flag[b], 0) == 0) { }
        pre += g_bsum[b];
    }
    sp[tid] = pre;
    __syncthreads();
    #pragma unroll
    for (int off = 128; off > 0; off >>= 1) {
        if (tid < off) sp[tid] += sp[tid + off];
        __syncthreads();
    }
    int base = sp[0];
    if (i < NN) {
        g_offsets[i] = base + s[tid] - v;
        g_cursor[i] = 0;
    }
    if (blockIdx.x == NSCAN - 1 && tid == 255) g_offsets[NN] = base + s[255];
}
__global__ void scatter_kernel(const int* __restrict__ src, const int* __restrict__ dst, int E) {
    int q = blockIdx.x * blockDim.x + threadIdx.x;
    int e = q * 4;
    if (e + 4 <= E) {
        int4 d = *(const int4*)(dst + e);
        int4 sv = *(const int4*)(src + e);
        int p;
        p = atomicAdd(&g_cursor[d.x], 1); g_esrc[g_offsets[d.x] + p] = sv.x;
        p = atomicAdd(&g_cursor[d.y], 1); g_esrc[g_offsets[d.y] + p] = sv.y;
        p = atomicAdd(&g_cursor[d.z], 1); g_esrc[g_offsets[d.z] + p] = sv.z;
        p = atomicAdd(&g_cursor[d.w], 1); g_esrc[g_offsets[d.w] + p] = sv.w;
    } else {
        for (int k = e; k < E; k++) {
            int d = dst[k];
            int p = atomicAdd(&g_cursor[d], 1);
            g_esrc[g_offsets[d] + p] = src[k];
        }
    }
}

// ======================= conversion =======================
__global__ void conv_x_kernel(const float* __restrict__ x) {
    int i = blockIdx.x * blockDim.x + threadIdx.x;
    if (i < NN * 128) g_Xh[i] = __float2half(x[i]);
}
#define W0_ELEMS (256 * 256)
#define W12_ELEMS (256 * 512)
__global__ void conv_w_all_kernel(const float* __restrict__ Wl0, const float* __restrict__ Wr0,
                                  const float* __restrict__ Wl1, const float* __restrict__ Wr1,
                                  const float* __restrict__ Wl2, const float* __restrict__ Wr2,
                                  __half* __restrict__ Bf) {
    int i = blockIdx.x * blockDim.x + threadIdx.x;
    int tot = W0_ELEMS + 2 * W12_ELEMS;
    if (i >= tot) return;
    const float *Wl, *Wr;
    int r, K;
    if (i < W0_ELEMS) { Wl = Wl0; Wr = Wr0; K = 128; r = i; }
    else if (i < W0_ELEMS + W12_ELEMS) { Wl = Wl1; Wr = Wr1; K = 256; r = i - W0_ELEMS; }
    else { Wl = Wl2; Wr = Wr2; K = 256; r = i - W0_ELEMS - W12_ELEMS; }
    int n = r / (2 * K);
    int k = r - n * 2 * K;
    float f = (k < K) ? Wl[k * 256 + n] : Wr[(k - K) * 256 + n];
    g_Bf[i] = __float2half(f);
}

// ======================= mean aggregation: one warp per node, 128-thread blocks =======================
template <bool WIDE>
__global__ __launch_bounds__(128) void agg_f16(const __half* __restrict__ h,
                                               __half* __restrict__ mean,
                                               int nodeBeg, int nodeEnd) {
    int w = (blockIdx.x * blockDim.x + threadIdx.x) >> 5;
    int node = nodeBeg + w;
    if (node >= nodeEnd) return;
    int lane = threadIdx.x & 31;
    int beg = g_offsets[node], end = g_offsets[node + 1];

    if (WIDE) {
        const uint4* base = reinterpret_cast<const uint4*>(h) + lane;
        float a0 = 0.f, a1 = 0.f, a2 = 0.f, a3 = 0.f, a4 = 0.f, a5 = 0.f, a6 = 0.f, a7 = 0.f;
        int e = beg;
        for (; e + 2 <= end; e += 2) {
            int s0 = g_esrc[e];
            int s1 = g_esrc[e + 1];
            uint4 t0 = __ldg(base + (size_t)s0 * 32);
            uint4 t1 = __ldg(base + (size_t)s1 * 32);
            float2 f;
            f = __half22float2(*(const __half2*)&t0.x); a0 += f.x; a1 += f.y;
            f = __half22float2(*(const __half2*)&t0.y); a2 += f.x; a3 += f.y;
            f = __half22float2(*(const __half2*)&t0.z); a4 += f.x; a5 += f.y;
            f = __half22float2(*(const __half2*)&t0.w); a6 += f.x; a7 += f.y;
            f = __half22float2(*(const __half2*)&t1.x); a0 += f.x; a1 += f.y;
            f = __half22float2(*(const __half2*)&t1.y); a2 += f.x; a3 += f.y;
            f = __half22float2(*(const __half2*)&t1.z); a4 += f.x; a5 += f.y;
            f = __half22float2(*(const __half2*)&t1.w); a6 += f.x; a7 += f.y;
        }
        for (; e < end; e++) {
            int s = g_esrc[e];
            uint4 t = __ldg(base + (size_t)s * 32);
            float2 f;
            f = __half22float2(*(const __half2*)&t.x); a0 += f.x; a1 += f.y;
            f = __half22float2(*(const __half2*)&t.y); a2 += f.x; a3 += f.y;
            f = __half22float2(*(const __half2*)&t.z); a4 += f.x; a5 += f.y;
            f = __half22float2(*(const __half2*)&t.w); a6 += f.x; a7 += f.y;
        }
        int deg = end - beg;
        float inv = 1.0f / (float)(deg > 1 ? deg : 1);
        __half2 p0 = __floats2half2_rn(a0 * inv, a1 * inv);
        __half2 p1 = __floats2half2_rn(a2 * inv, a3 * inv);
        __half2 p2 = __floats2half2_rn(a4 * inv, a5 * inv);
        __half2 p3 = __floats2half2_rn(a6 * inv, a7 * inv);
        uint4 o;
        o.x = *(uint32_t*)&p0; o.y = *(uint32_t*)&p1;
        o.z = *(uint32_t*)&p2; o.w = *(uint32_t*)&p3;
        reinterpret_cast<uint4*>(mean)[(size_t)node * 32 + lane] = o;
    } else {
        const uint2* base = reinterpret_cast<const uint2*>(h) + lane;
        float a0 = 0.f, a1 = 0.f, a2 = 0.f, a3 = 0.f;
        int e = beg;
        for (; e + 2 <= end; e += 2) {
            int s0 = g_esrc[e];
            int s1 = g_esrc[e + 1];
            uint2 t0 = __ldg(base + (size_t)s0 * 32);
            uint2 t1 = __ldg(base + (size_t)s1 * 32);
            float2 f;
            f = __half22float2(*(const __half2*)&t0.x); a0 += f.x; a1 += f.y;
            f = __half22float2(*(const __half2*)&t0.y); a2 += f.x; a3 += f.y;
            f = __half22float2(*(const __half2*)&t1.x); a0 += f.x; a1 += f.y;
            f = __half22float2(*(const __half2*)&t1.y); a2 += f.x; a3 += f.y;
        }
        for (; e < end; e++) {
            int s = g_esrc[e];
            uint2 t = __ldg(base + (size_t)s * 32);
            float2 f;
            f = __half22float2(*(const __half2*)&t.x); a0 += f.x; a1 += f.y;
            f = __half22float2(*(const __half2*)&t.y); a2 += f.x; a3 += f.y;
        }
        int deg = end - beg;
        float inv = 1.0f / (float)(deg > 1 ? deg : 1);
        __half2 p0 = __floats2half2_rn(a0 * inv, a1 * inv);
        __half2 p1 = __floats2half2_rn(a2 * inv, a3 * inv);
        uint2 o;
        o.x = *(uint32_t*)&p0; o.y = *(uint32_t*)&p1;
        reinterpret_cast<uint2*>(mean)[(size_t)node * 32 + lane] = o;
    }
}

// ======================= fp16 mma.sync helper =======================
__device__ __forceinline__ void mma16816(float* c, const uint32_t* a, uint32_t b0, uint32_t b1) {
    asm("mma.sync.aligned.m16n8k16.row.col.f32.f16.f16.f32 "
        "{%0,%1,%2,%3}, {%4,%5,%6,%7}, {%8,%9}, {%0,%1,%2,%3};"
        : "+f"(c[0]), "+f"(c[1]), "+f"(c[2]), "+f"(c[3])
        : "r"(a[0]), "r"(a[1]), "r"(a[2]), "r"(a[3]), "r"(b0), "r"(b1));
}

// ======================= concat dual-source 3-stage GEMM =======================
#define SST 40
#define PLANE_B (128 * SST * 2)
#define BUF_B   (2 * PLANE_B)
#define NSTAGE  3
#define GSMEM   (NSTAGE * BUF_B)

template <int KH, bool PACK_OUT, bool RELU>
__global__ __launch_bounds__(256, 2) void gemm_cat(
    const __half* __restrict__ A1, const __half* __restrict__ A2,
    const __half* __restrict__ Bf,
    const float* __restrict__ blv, const float* __restrict__ gam,
    const float* __restrict__ bet, const float* __restrict__ rm,
    const float* __restrict__ rv,
    float* __restrict__ outf, __half* __restrict__ outh, int rowOff, int M)
{
    extern __shared__ __align__(16) char dsm[];
    constexpr int NC = 2 * KH / 32;
    constexpr int NC1 = KH / 32;

    int tid = threadIdx.x;
    int lane = tid & 31;
    int wid = tid >> 5;
    int g = lane >> 2;
    int tig = lane & 3;
    int wm = wid & 3;
    int wn = wid >> 2;
    int mBase = rowOff + blockIdx.x * 128;
    int nBase = blockIdx.y * 128;

    float acc[2][8][4];
    #pragma unroll
    for (int mt = 0; mt < 2; mt++)
        #pragma unroll
        for (int nt = 0; nt < 8; nt++)
            #pragma unroll
            for (int q = 0; q < 4; q++) acc[mt][nt][q] = 0.f;

    auto stageAB = [&](int kc, int buf) {
        char* base = dsm + buf * BUF_B;
        uint32_t dA = (uint32_t)__cvta_generic_to_shared(base);
        uint32_t dB = (uint32_t)__cvta_generic_to_shared(base + PLANE_B);
        const __half* Asrc = (kc < NC1) ? A1 : A2;
        int kOff = (kc < NC1) ? kc * 32 : (kc - NC1) * 32;
        #pragma unroll
        for (int i = 0; i < 2; i++) {
            int lin = tid + i * 256;
            int row = lin >> 2;
            int c8 = lin & 3;
            uint32_t doff = (uint32_t)(row * (SST * 2) + c8 * 16);
            int grow = mBase + row;
            int ok = (grow < M);
            int gr = ok ? grow : (M - 1);
            cpasync16z(dA + doff, Asrc + (size_t)gr * KH + kOff + c8 * 8, ok ? 16 : 0);
            cpasync16(dB + doff, Bf + (size_t)(nBase + row) * (2 * KH) + kc * 32 + c8 * 8);
        }
        cpcommit();
    };

    stageAB(0, 0);
    stageAB(1, 1);

    for (int kc = 0; kc < NC; kc++) {
        if (kc + 2 < NC) stageAB(kc + 2, (kc + 2) % NSTAGE);
        int rem = NC - 1 - kc;
        if (rem >= 2) cpwait2();
        else if (rem == 1) cpwait1();
        else cpwait0();
        __syncthreads();
        {
            char* base = dsm + (kc % NSTAGE) * BUF_B;
            const __half* sA = (const __half*)base;
            const __half* sB = (const __half*)(base + PLANE_B);
            #pragma unroll
            for (int ks = 0; ks < 2; ks++) {
                int k0 = ks * 16;
                uint32_t ah[2][4];
                #pragma unroll
                for (int mt = 0; mt < 2; mt++) {
                    int r0 = (wm * 32 + mt * 16 + g) * SST + k0 + 2 * tig;
                    ah[mt][0] = *(const uint32_t*)&sA[r0];
                    ah[mt][1] = *(const uint32_t*)&sA[r0 + 8 * SST];
                    ah[mt][2] = *(const uint32_t*)&sA[r0 + 8];
                    ah[mt][3] = *(const uint32_t*)&sA[r0 + 8 * SST + 8];
                }
                #pragma unroll
                for (int nt = 0; nt < 8; nt++) {
                    int b0 = (wn * 64 + nt * 8 + g) * SST + k0 + 2 * tig;
                    uint32_t bv0 = *(const uint32_t*)&sB[b0];
                    uint32_t bv1 = *(const uint32_t*)&sB[b0 + 8];
                    #pragma unroll
                    for (int mt = 0; mt < 2; mt++)
                        mma16816(acc[mt][nt], ah[mt], bv0, bv1);
                }
            }
        }
        __syncthreads();
    }

    #pragma unroll
    for (int nt = 0; nt < 8; nt++) {
        int c0 = nBase + wn * 64 + nt * 8 + 2 * tig;
        int c1 = c0 + 1;
        float sc0 = gam[c0] * rsqrtf(rv[c0] + EPS);
        float sh0 = (blv[c0] - rm[c0]) * sc0 + bet[c0];
        float sc1 = gam[c1] * rsqrtf(rv[c1] + EPS);
        float sh1 = (blv[c1] - rm[c1]) * sc1 + bet[c1];
        #pragma unroll
        for (int mt = 0; mt < 2; mt++) {
            int r0 = mBase + wm * 32 + mt * 16 + g;
            int r1 = r0 + 8;
            if (r0 < M) {
                float v00 = acc[mt][nt][0] * sc0 + sh0;
                float v01 = acc[mt][nt][1] * sc1 + sh1;
                if (RELU) { v00 = fmaxf(v00, 0.f); v01 = fmaxf(v01, 0.f); }
                if (PACK_OUT) {
                    __half2 hv = __floats2half2_rn(v00, v01);
                    *(__half2*)(outh + (size_t)r0 * 256 + c0) = hv;
                } else {
                    *(float2*)(outf + (size_t)r0 * 256 + c0) = make_float2(v00, v01);
                }
            }
            if (r1 < M) {
                float v10 = acc[mt][nt][2] * sc0 + sh0;
                float v11 = acc[mt][nt][3] * sc1 + sh1;
                if (RELU) { v10 = fmaxf(v10, 0.f); v11 = fmaxf(v11, 0.f); }
                if (PACK_OUT) {
                    __half2 hv = __floats2half2_rn(v10, v11);
                    *(__half2*)(outh + (size_t)r1 * 256 + c0) = hv;
                } else {
                    *(float2*)(outf + (size_t)r1 * 256 + c0) = make_float2(v10, v11);
                }
            }
        }
    }
}

// ======================= launch =======================
extern "C" void kernel_launch(void* const* d_in, const int* in_sizes, int n_in,
                              void* d_out, int out_size) {
    const float* x = (const float*)d_in[0];
    const int* ei = (const int*)d_in[1];
    int E = in_sizes[1] / 2;
    const int* src = ei;
    const int* dst = ei + E;

    const float* Wl0 = (const float*)d_in[2];
    const float* bl0 = (const float*)d_in[3];
    const float* Wr0 = (const float*)d_in[4];
    const float* g0 = (const float*)d_in[5];
    const float* b0 = (const float*)d_in[6];
    const float* rm0 = (const float*)d_in[7];
    const float* rv0 = (const float*)d_in[8];
    const float* Wl1 = (const float*)d_in[9];
    const float* bl1 = (const float*)d_in[10];
    const float* Wr1 = (const float*)d_in[11];
    const float* g1 = (const float*)d_in[12];
    const float* b1 = (const float*)d_in[13];
    const float* rm1 = (const float*)d_in[14];
    const float* rv1 = (const float*)d_in[15];
    const float* Wl2 = (const float*)d_in[16];
    const float* bl2 = (const float*)d_in[17];
    const float* Wr2 = (const float*)d_in[18];
    const float* g2 = (const float*)d_in[19];
    const float* b2 = (const float*)d_in[20];
    const float* rm2 = (const float*)d_in[21];
    const float* rv2 = (const float*)d_in[22];

    __half *Xh, *h1h, *h2h, *Mh, *Bf;
    cudaGetSymbolAddress((void**)&Xh, g_Xh);
    cudaGetSymbolAddress((void**)&h1h, g_h1h);
    cudaGetSymbolAddress((void**)&h2h, g_h2h);
    cudaGetSymbolAddress((void**)&Mh, g_Mh);
    cudaGetSymbolAddress((void**)&Bf, g_Bf);
    __half* Bf0 = Bf;
    __half* Bf1 = Bf0 + 256 * 256;
    __half* Bf2 = Bf1 + 256 * 512;

    cudaFuncSetAttribute(gemm_cat<128, true, true>, cudaFuncAttributeMaxDynamicSharedMemorySize, GSMEM);
    cudaFuncSetAttribute(gemm_cat<256, true, true>, cudaFuncAttributeMaxDynamicSharedMemorySize, GSMEM);
    cudaFuncSetAttribute(gemm_cat<256, false, false>, cudaFuncAttributeMaxDynamicSharedMemorySize, GSMEM);

    cudaStream_t s1, s2;
    cudaStreamCreateWithFlags(&s1, cudaStreamNonBlocking);
    cudaStreamCreateWithFlags(&s2, cudaStreamNonBlocking);

    cudaEvent_t evRoot, evX, evW, evA[3][NCHUNK], evGlast[3];
    cudaEventCreateWithFlags(&evRoot, cudaEventDisableTiming);
    cudaEventCreateWithFlags(&evX, cudaEventDisableTiming);
    cudaEventCreateWithFlags(&evW, cudaEventDisableTiming);
    for (int l = 0; l < 3; l++) {
        for (int c = 0; c < NCHUNK; c++)
            cudaEventCreateWithFlags(&evA[l][c], cudaEventDisableTiming);
        cudaEventCreateWithFlags(&evGlast[l], cudaEventDisableTiming);
    }

    // chunk bounds
    int cb[NCHUNK + 1];
    for (int c = 0; c < NCHUNK; c++) cb[c] = c * CHUNK;
    cb[NCHUNK] = NN;

    auto aggBlocks = [](int nodes) { return (nodes * 32 + 127) / 128; };
    int nEdgeQuads = (E + 1023) / 1024;

    cudaEventRecord(evRoot, 0);
    cudaStreamWaitEvent(s1, evRoot, 0);
    cudaStreamWaitEvent(s2, evRoot, 0);

    // ---- s1: conversions ----
    conv_x_kernel<<<(NN * 128 + 255) / 256, 256, 0, s1>>>(x);
    cudaEventRecord(evX, s1);
    conv_w_all_kernel<<<(W0_ELEMS + 2 * W12_ELEMS + 255) / 256, 256, 0, s1>>>(
        Wl0, Wr0, Wl1, Wr1, Wl2, Wr2, Bf);
    cudaEventRecord(evW, s1);

    // ---- main: CSR build ----
    zero_counts_kernel<<<(NN + 255) / 256, 256>>>();
    hist_kernel<<<nEdgeQuads, 256>>>(dst, E);
    scan_fused_kernel<<<NSCAN, 256>>>();
    scatter_kernel<<<nEdgeQuads, 256>>>(src, dst, E);

    // =========== layer 0 (agg reads Xh, gemm -> h1h) ===========
    cudaStreamWaitEvent(0, evX, 0);
    cudaStreamWaitEvent(s2, evW, 0);
    for (int c = 0; c < NCHUNK; c++) {
        agg_f16<false><<<aggBlocks(cb[c + 1] - cb[c]), 128>>>(Xh, Mh, cb[c], cb[c + 1]);
        cudaEventRecord(evA[0][c], 0);
        cudaStreamWaitEvent(s2, evA[0][c], 0);
        dim3 gg((cb[c + 1] - cb[c] + 127) / 128, 2);
        gemm_cat<128, true, true><<<gg, 256, GSMEM, s2>>>(
            Mh, Xh, Bf0, bl0, g0, b0, rm0, rv0, nullptr, h1h, cb[c], NN);
    }
    cudaEventRecord(evGlast[0], s2);
    cudaStreamWaitEvent(0, evGlast[0], 0);

    // =========== layer 1 (agg reads h1h, gemm -> h2h) ===========
    for (int c = 0; c < NCHUNK; c++) {
        agg_f16<true><<<aggBlocks(cb[c + 1] - cb[c]), 128>>>(h1h, Mh, cb[c], cb[c + 1]);
        cudaEventRecord(evA[1][c], 0);
        cudaStreamWaitEvent(s2, evA[1][c], 0);
        dim3 gg((cb[c + 1] - cb[c] + 127) / 128, 2);
        gemm_cat<256, true, true><<<gg, 256, GSMEM, s2>>>(
            Mh, h1h, Bf1, bl1, g1, b1, rm1, rv1, nullptr, h2h, cb[c], NN);
    }
    cudaEventRecord(evGlast[1], s2);
    cudaStreamWaitEvent(0, evGlast[1], 0);

    // =========== layer 2 (agg reads h2h, gemm -> d_out fp32) ===========
    for (int c = 0; c < NCHUNK; c++) {
        agg_f16<true><<<aggBlocks(cb[c + 1] - cb[c]), 128>>>(h2h, Mh, cb[c], cb[c + 1]);
        cudaEventRecord(evA[2][c], 0);
        cudaStreamWaitEvent(s2, evA[2][c], 0);
        dim3 gg((cb[c + 1] - cb[c] + 127) / 128, 2);
        gemm_cat<256, false, false><<<gg, 256, GSMEM, s2>>>(
            Mh, h2h, Bf2, bl2, g2, b2, rm2, rv2, (float*)d_out, nullptr, cb[c], NN);
    }
    cudaEventRecord(evGlast[2], s2);
    cudaStreamWaitEvent(0, evGlast[2], 0);

    cudaEventDestroy(evRoot);
    cudaEventDestroy(evX);
    cudaEventDestroy(evW);
    for (int l = 0; l < 3; l++) {
        for (int c = 0; c < NCHUNK; c++) cudaEventDestroy(evA[l][c]);
        cudaEventDestroy(evGlast[l]);
    }
    cudaStreamDestroy(s1);
    cudaStreamDestroy(s2);
}

// round 15
// speedup vs baseline: 1.1846x; 1.1846x over previous
#include <cuda_runtime.h>
#include <cuda_fp16.h>
#include <cstdint>

#define NN 50000
#define EMAX 800000
#define EPS 1e-5f
#define HALF0 25088   // 196 * 128
#define NSCAN 196     // ceil(NN/256)

__device__ __forceinline__ void cpasync16(uint32_t dst, const void* src) {
    asm volatile("cp.async.cg.shared.global [%0], [%1], 16;" :: "r"(dst), "l"(src));
}
__device__ __forceinline__ void cpasync16z(uint32_t dst, const void* src, int size) {
    asm volatile("cp.async.cg.shared.global [%0], [%1], 16, %2;" :: "r"(dst), "l"(src), "r"(size));
}
__device__ __forceinline__ void cpcommit() { asm volatile("cp.async.commit_group;" ::: "memory"); }
__device__ __forceinline__ void cpwait0() { asm volatile("cp.async.wait_group 0;" ::: "memory"); }
__device__ __forceinline__ void cpwait1() { asm volatile("cp.async.wait_group 1;" ::: "memory"); }
__device__ __forceinline__ void cpwait2() { asm volatile("cp.async.wait_group 2;" ::: "memory"); }

// ======================= scratch =======================
__device__ __half g_Xh[NN * 128];
__device__ __half g_h1h[NN * 256];
__device__ __half g_h2h[NN * 256];
__device__ __half g_Mh[NN * 256];
__device__ __align__(16) __half g_Bf[256 * 256 + 2 * 256 * 512];
__device__ int g_counts[NN];
__device__ int g_offsets[NN + 1];
__device__ int g_cursor[NN];
__device__ int g_esrc[EMAX];
__device__ int g_bsum[NSCAN];
__device__ int g_flag[NSCAN];

// ======================= CSR build =======================
__global__ void zero_counts_kernel() {
    int i = blockIdx.x * blockDim.x + threadIdx.x;
    if (i < NN) g_counts[i] = 0;
    if (i < NSCAN) g_flag[i] = 0;
}
__global__ void hist_kernel(const int* __restrict__ dst, int E) {
    int q = blockIdx.x * blockDim.x + threadIdx.x;
    int e = q * 4;
    if (e + 4 <= E) {
        int4 d = *(const int4*)(dst + e);
        atomicAdd(&g_counts[d.x], 1);
        atomicAdd(&g_counts[d.y], 1);
        atomicAdd(&g_counts[d.z], 1);
        atomicAdd(&g_counts[d.w], 1);
    } else {
        for (int k = e; k < E; k++) atomicAdd(&g_counts[dst[k]], 1);
    }
}
__global__ void scan_fused_kernel() {
    __shared__ int s[256];
    __shared__ int sp[256];
    int tid = threadIdx.x;
    int i = blockIdx.x * 256 + tid;
    int v = (i < NN) ? g_counts[i] : 0;
    s[tid] = v;
    __syncthreads();
    #pragma unroll
    for (int off = 1; off < 256; off <<= 1) {
        int t = (tid >= off) ? s[tid - off] : 0;
        __syncthreads();
        s[tid] += t;
        __syncthreads();
    }
    if (tid == 255) {
        g_bsum[blockIdx.x] = s[255];
        __threadfence();
        atomicExch(&g_flag[blockIdx.x], 1);
    }
    int pre = 0;
    for (int b = tid; b < blockIdx.x; b += 256) {
        while (atomicAdd(&g_flag[b], 0) == 0) { }
        pre += g_bsum[b];
    }
    sp[tid] = pre;
    __syncthreads();
    #pragma unroll
    for (int off = 128; off > 0; off >>= 1) {
        if (tid < off) sp[tid] += sp[tid + off];
        __syncthreads();
    }
    int base = sp[0];
    if (i < NN) {
        g_offsets[i] = base + s[tid] - v;
        g_cursor[i] = 0;
    }
    if (blockIdx.x == NSCAN - 1 && tid == 255) g_offsets[NN] = base + s[255];
}
__global__ void scatter_kernel(const int* __restrict__ src, const int* __restrict__ dst, int E) {
    int q = blockIdx.x * blockDim.x + threadIdx.x;
    int e = q * 4;
    if (e + 4 <= E) {
        int4 d = *(const int4*)(dst + e);
        int4 sv = *(const int4*)(src + e);
        int p;
        p = atomicAdd(&g_cursor[d.x], 1); g_esrc[g_offsets[d.x] + p] = sv.x;
        p = atomicAdd(&g_cursor[d.y], 1); g_esrc[g_offsets[d.y] + p] = sv.y;
        p = atomicAdd(&g_cursor[d.z], 1); g_esrc[g_offsets[d.z] + p] = sv.z;
        p = atomicAdd(&g_cursor[d.w], 1); g_esrc[g_offsets[d.w] + p] = sv.w;
    } else {
        for (int k = e; k < E; k++) {
            int d = dst[k];
            int p = atomicAdd(&g_cursor[d], 1);
            g_esrc[g_offsets[d] + p] = src[k];
        }
    }
}

// ======================= conversion =======================
__global__ void conv_x_kernel(const float* __restrict__ x) {
    int i = blockIdx.x * blockDim.x + threadIdx.x;
    if (i < NN * 128) g_Xh[i] = __float2half(x[i]);
}
#define W0_ELEMS (256 * 256)
#define W12_ELEMS (256 * 512)
__global__ void conv_w_all_kernel(const float* __restrict__ Wl0, const float* __restrict__ Wr0,
                                  const float* __restrict__ Wl1, const float* __restrict__ Wr1,
                                  const float* __restrict__ Wl2, const float* __restrict__ Wr2,
                                  __half* __restrict__ Bf) {
    int i = blockIdx.x * blockDim.x + threadIdx.x;
    int tot = W0_ELEMS + 2 * W12_ELEMS;
    if (i >= tot) return;
    const float *Wl, *Wr;
    int r, K;
    if (i < W0_ELEMS) { Wl = Wl0; Wr = Wr0; K = 128; r = i; }
    else if (i < W0_ELEMS + W12_ELEMS) { Wl = Wl1; Wr = Wr1; K = 256; r = i - W0_ELEMS; }
    else { Wl = Wl2; Wr = Wr2; K = 256; r = i - W0_ELEMS - W12_ELEMS; }
    int n = r / (2 * K);
    int k = r - n * 2 * K;
    float f = (k < K) ? Wl[k * 256 + n] : Wr[(k - K) * 256 + n];
    g_Bf[i] = __float2half(f);
}

// ======================= mean aggregation: one warp per node, edge-unroll x4 =======================
template <bool WIDE>
__global__ __launch_bounds__(256) void agg_f16(const __half* __restrict__ h,
                                               __half* __restrict__ mean,
                                               int nodeBeg, int nodeEnd) {
    int w = (blockIdx.x * blockDim.x + threadIdx.x) >> 5;
    int node = nodeBeg + w;
    if (node >= nodeEnd) return;
    int lane = threadIdx.x & 31;
    int beg = g_offsets[node], end = g_offsets[node + 1];

    if (WIDE) {
        const uint4* base = reinterpret_cast<const uint4*>(h) + lane;
        float a0 = 0.f, a1 = 0.f, a2 = 0.f, a3 = 0.f, a4 = 0.f, a5 = 0.f, a6 = 0.f, a7 = 0.f;
        int e = beg;
        for (; e + 4 <= end; e += 4) {
            int s0 = g_esrc[e];
            int s1 = g_esrc[e + 1];
            int s2 = g_esrc[e + 2];
            int s3 = g_esrc[e + 3];
            uint4 t0 = __ldg(base + (size_t)s0 * 32);
            uint4 t1 = __ldg(base + (size_t)s1 * 32);
            uint4 t2 = __ldg(base + (size_t)s2 * 32);
            uint4 t3 = __ldg(base + (size_t)s3 * 32);
            float2 f;
            f = __half22float2(*(const __half2*)&t0.x); a0 += f.x; a1 += f.y;
            f = __half22float2(*(const __half2*)&t0.y); a2 += f.x; a3 += f.y;
            f = __half22float2(*(const __half2*)&t0.z); a4 += f.x; a5 += f.y;
            f = __half22float2(*(const __half2*)&t0.w); a6 += f.x; a7 += f.y;
            f = __half22float2(*(const __half2*)&t1.x); a0 += f.x; a1 += f.y;
            f = __half22float2(*(const __half2*)&t1.y); a2 += f.x; a3 += f.y;
            f = __half22float2(*(const __half2*)&t1.z); a4 += f.x; a5 += f.y;
            f = __half22float2(*(const __half2*)&t1.w); a6 += f.x; a7 += f.y;
            f = __half22float2(*(const __half2*)&t2.x); a0 += f.x; a1 += f.y;
            f = __half22float2(*(const __half2*)&t2.y); a2 += f.x; a3 += f.y;
            f = __half22float2(*(const __half2*)&t2.z); a4 += f.x; a5 += f.y;
            f = __half22float2(*(const __half2*)&t2.w); a6 += f.x; a7 += f.y;
            f = __half22float2(*(const __half2*)&t3.x); a0 += f.x; a1 += f.y;
            f = __half22float2(*(const __half2*)&t3.y); a2 += f.x; a3 += f.y;
            f = __half22float2(*(const __half2*)&t3.z); a4 += f.x; a5 += f.y;
            f = __half22float2(*(const __half2*)&t3.w); a6 += f.x; a7 += f.y;
        }
        for (; e < end; e++) {
            int s = g_esrc[e];
            uint4 t = __ldg(base + (size_t)s * 32);
            float2 f;
            f = __half22float2(*(const __half2*)&t.x); a0 += f.x; a1 += f.y;
            f = __half22float2(*(const __half2*)&t.y); a2 += f.x; a3 += f.y;
            f = __half22float2(*(const __half2*)&t.z); a4 += f.x; a5 += f.y;
            f = __half22float2(*(const __half2*)&t.w); a6 += f.x; a7 += f.y;
        }
        int deg = end - beg;
        float inv = 1.0f / (float)(deg > 1 ? deg : 1);
        __half2 p0 = __floats2half2_rn(a0 * inv, a1 * inv);
        __half2 p1 = __floats2half2_rn(a2 * inv, a3 * inv);
        __half2 p2 = __floats2half2_rn(a4 * inv, a5 * inv);
        __half2 p3 = __floats2half2_rn(a6 * inv, a7 * inv);
        uint4 o;
        o.x = *(uint32_t*)&p0; o.y = *(uint32_t*)&p1;
        o.z = *(uint32_t*)&p2; o.w = *(uint32_t*)&p3;
        reinterpret_cast<uint4*>(mean)[(size_t)node * 32 + lane] = o;
    } else {
        const uint2* base = reinterpret_cast<const uint2*>(h) + lane;
        float a0 = 0.f, a1 = 0.f, a2 = 0.f, a3 = 0.f;
        int e = beg;
        for (; e + 4 <= end; e += 4) {
            int s0 = g_esrc[e];
            int s1 = g_esrc[e + 1];
            int s2 = g_esrc[e + 2];
            int s3 = g_esrc[e + 3];
            uint2 t0 = __ldg(base + (size_t)s0 * 32);
            uint2 t1 = __ldg(base + (size_t)s1 * 32);
            uint2 t2 = __ldg(base + (size_t)s2 * 32);
            uint2 t3 = __ldg(base + (size_t)s3 * 32);
            float2 f;
            f = __half22float2(*(const __half2*)&t0.x); a0 += f.x; a1 += f.y;
            f = __half22float2(*(const __half2*)&t0.y); a2 += f.x; a3 += f.y;
            f = __half22float2(*(const __half2*)&t1.x); a0 += f.x; a1 += f.y;
            f = __half22float2(*(const __half2*)&t1.y); a2 += f.x; a3 += f.y;
            f = __half22float2(*(const __half2*)&t2.x); a0 += f.x; a1 += f.y;
            f = __half22float2(*(const __half2*)&t2.y); a2 += f.x; a3 += f.y;
            f = __half22float2(*(const __half2*)&t3.x); a0 += f.x; a1 += f.y;
            f = __half22float2(*(const __half2*)&t3.y); a2 += f.x; a3 += f.y;
        }
        for (; e < end; e++) {
            int s = g_esrc[e];
            uint2 t = __ldg(base + (size_t)s * 32);
            float2 f;
            f = __half22float2(*(const __half2*)&t.x); a0 += f.x; a1 += f.y;
            f = __half22float2(*(const __half2*)&t.y); a2 += f.x; a3 += f.y;
        }
        int deg = end - beg;
        float inv = 1.0f / (float)(deg > 1 ? deg : 1);
        __half2 p0 = __floats2half2_rn(a0 * inv, a1 * inv);
        __half2 p1 = __floats2half2_rn(a2 * inv, a3 * inv);
        uint2 o;
        o.x = *(uint32_t*)&p0; o.y = *(uint32_t*)&p1;
        reinterpret_cast<uint2*>(mean)[(size_t)node * 32 + lane] = o;
    }
}

// ======================= fp16 mma.sync helper =======================
__device__ __forceinline__ void mma16816(float* c, const uint32_t* a, uint32_t b0, uint32_t b1) {
    asm("mma.sync.aligned.m16n8k16.row.col.f32.f16.f16.f32 "
        "{%0,%1,%2,%3}, {%4,%5,%6,%7}, {%8,%9}, {%0,%1,%2,%3};"
        : "+f"(c[0]), "+f"(c[1]), "+f"(c[2]), "+f"(c[3])
        : "r"(a[0]), "r"(a[1]), "r"(a[2]), "r"(a[3]), "r"(b0), "r"(b1));
}

// ======================= concat dual-source 3-stage GEMM =======================
#define SST 40
#define PLANE_B (128 * SST * 2)
#define BUF_B   (2 * PLANE_B)
#define NSTAGE  3
#define GSMEM   (NSTAGE * BUF_B)

template <int KH, bool PACK_OUT, bool RELU>
__global__ __launch_bounds__(256, 2) void gemm_cat(
    const __half* __restrict__ A1, const __half* __restrict__ A2,
    const __half* __restrict__ Bf,
    const float* __restrict__ blv, const float* __restrict__ gam,
    const float* __restrict__ bet, const float* __restrict__ rm,
    const float* __restrict__ rv,
    float* __restrict__ outf, __half* __restrict__ outh, int rowOff, int M)
{
    extern __shared__ __align__(16) char dsm[];
    constexpr int NC = 2 * KH / 32;
    constexpr int NC1 = KH / 32;

    int tid = threadIdx.x;
    int lane = tid & 31;
    int wid = tid >> 5;
    int g = lane >> 2;
    int tig = lane & 3;
    int wm = wid & 3;
    int wn = wid >> 2;
    int mBase = rowOff + blockIdx.x * 128;
    int nBase = blockIdx.y * 128;

    float acc[2][8][4];
    #pragma unroll
    for (int mt = 0; mt < 2; mt++)
        #pragma unroll
        for (int nt = 0; nt < 8; nt++)
            #pragma unroll
            for (int q = 0; q < 4; q++) acc[mt][nt][q] = 0.f;

    auto stageAB = [&](int kc, int buf) {
        char* base = dsm + buf * BUF_B;
        uint32_t dA = (uint32_t)__cvta_generic_to_shared(base);
        uint32_t dB = (uint32_t)__cvta_generic_to_shared(base + PLANE_B);
        const __half* Asrc = (kc < NC1) ? A1 : A2;
        int kOff = (kc < NC1) ? kc * 32 : (kc - NC1) * 32;
        #pragma unroll
        for (int i = 0; i < 2; i++) {
            int lin = tid + i * 256;
            int row = lin >> 2;
            int c8 = lin & 3;
            uint32_t doff = (uint32_t)(row * (SST * 2) + c8 * 16);
            int grow = mBase + row;
            int ok = (grow < M);
            int gr = ok ? grow : (M - 1);
            cpasync16z(dA + doff, Asrc + (size_t)gr * KH + kOff + c8 * 8, ok ? 16 : 0);
            cpasync16(dB + doff, Bf + (size_t)(nBase + row) * (2 * KH) + kc * 32 + c8 * 8);
        }
        cpcommit();
    };

    stageAB(0, 0);
    stageAB(1, 1);

    for (int kc = 0; kc < NC; kc++) {
        if (kc + 2 < NC) stageAB(kc + 2, (kc + 2) % NSTAGE);
        int rem = NC - 1 - kc;
        if (rem >= 2) cpwait2();
        else if (rem == 1) cpwait1();
        else cpwait0();
        __syncthreads();
        {
            char* base = dsm + (kc % NSTAGE) * BUF_B;
            const __half* sA = (const __half*)base;
            const __half* sB = (const __half*)(base + PLANE_B);
            #pragma unroll
            for (int ks = 0; ks < 2; ks++) {
                int k0 = ks * 16;
                uint32_t ah[2][4];
                #pragma unroll
                for (int mt = 0; mt < 2; mt++) {
                    int r0 = (wm * 32 + mt * 16 + g) * SST + k0 + 2 * tig;
                    ah[mt][0] = *(const uint32_t*)&sA[r0];
                    ah[mt][1] = *(const uint32_t*)&sA[r0 + 8 * SST];
                    ah[mt][2] = *(const uint32_t*)&sA[r0 + 8];
                    ah[mt][3] = *(const uint32_t*)&sA[r0 + 8 * SST + 8];
                }
                #pragma unroll
                for (int nt = 0; nt < 8; nt++) {
                    int b0 = (wn * 64 + nt * 8 + g) * SST + k0 + 2 * tig;
                    uint32_t bv0 = *(const uint32_t*)&sB[b0];
                    uint32_t bv1 = *(const uint32_t*)&sB[b0 + 8];
                    #pragma unroll
                    for (int mt = 0; mt < 2; mt++)
                        mma16816(acc[mt][nt], ah[mt], bv0, bv1);
                }
            }
        }
        __syncthreads();
    }

    #pragma unroll
    for (int nt = 0; nt < 8; nt++) {
        int c0 = nBase + wn * 64 + nt * 8 + 2 * tig;
        int c1 = c0 + 1;
        float sc0 = gam[c0] * rsqrtf(rv[c0] + EPS);
        float sh0 = (blv[c0] - rm[c0]) * sc0 + bet[c0];
        float sc1 = gam[c1] * rsqrtf(rv[c1] + EPS);
        float sh1 = (blv[c1] - rm[c1]) * sc1 + bet[c1];
        #pragma unroll
        for (int mt = 0; mt < 2; mt++) {
            int r0 = mBase + wm * 32 + mt * 16 + g;
            int r1 = r0 + 8;
            if (r0 < M) {
                float v00 = acc[mt][nt][0] * sc0 + sh0;
                float v01 = acc[mt][nt][1] * sc1 + sh1;
                if (RELU) { v00 = fmaxf(v00, 0.f); v01 = fmaxf(v01, 0.f); }
                if (PACK_OUT) {
                    __half2 hv = __floats2half2_rn(v00, v01);
                    *(__half2*)(outh + (size_t)r0 * 256 + c0) = hv;
                } else {
                    *(float2*)(outf + (size_t)r0 * 256 + c0) = make_float2(v00, v01);
                }
            }
            if (r1 < M) {
                float v10 = acc[mt][nt][2] * sc0 + sh0;
                float v11 = acc[mt][nt][3] * sc1 + sh1;
                if (RELU) { v10 = fmaxf(v10, 0.f); v11 = fmaxf(v11, 0.f); }
                if (PACK_OUT) {
                    __half2 hv = __floats2half2_rn(v10, v11);
                    *(__half2*)(outh + (size_t)r1 * 256 + c0) = hv;
                } else {
                    *(float2*)(outf + (size_t)r1 * 256 + c0) = make_float2(v10, v11);
                }
            }
        }
    }
}

// ======================= launch =======================
extern "C" void kernel_launch(void* const* d_in, const int* in_sizes, int n_in,
                              void* d_out, int out_size) {
    const float* x = (const float*)d_in[0];
    const int* ei = (const int*)d_in[1];
    int E = in_sizes[1] / 2;
    const int* src = ei;
    const int* dst = ei + E;

    const float* Wl0 = (const float*)d_in[2];
    const float* bl0 = (const float*)d_in[3];
    const float* Wr0 = (const float*)d_in[4];
    const float* g0 = (const float*)d_in[5];
    const float* b0 = (const float*)d_in[6];
    const float* rm0 = (const float*)d_in[7];
    const float* rv0 = (const float*)d_in[8];
    const float* Wl1 = (const float*)d_in[9];
    const float* bl1 = (const float*)d_in[10];
    const float* Wr1 = (const float*)d_in[11];
    const float* g1 = (const float*)d_in[12];
    const float* b1 = (const float*)d_in[13];
    const float* rm1 = (const float*)d_in[14];
    const float* rv1 = (const float*)d_in[15];
    const float* Wl2 = (const float*)d_in[16];
    const float* bl2 = (const float*)d_in[17];
    const float* Wr2 = (const float*)d_in[18];
    const float* g2 = (const float*)d_in[19];
    const float* b2 = (const float*)d_in[20];
    const float* rm2 = (const float*)d_in[21];
    const float* rv2 = (const float*)d_in[22];

    __half *Xh, *h1h, *h2h, *Mh, *Bf;
    cudaGetSymbolAddress((void**)&Xh, g_Xh);
    cudaGetSymbolAddress((void**)&h1h, g_h1h);
    cudaGetSymbolAddress((void**)&h2h, g_h2h);
    cudaGetSymbolAddress((void**)&Mh, g_Mh);
    cudaGetSymbolAddress((void**)&Bf, g_Bf);
    __half* Bf0 = Bf;
    __half* Bf1 = Bf0 + 256 * 256;
    __half* Bf2 = Bf1 + 256 * 512;

    cudaFuncSetAttribute(gemm_cat<128, true, true>, cudaFuncAttributeMaxDynamicSharedMemorySize, GSMEM);
    cudaFuncSetAttribute(gemm_cat<256, true, true>, cudaFuncAttributeMaxDynamicSharedMemorySize, GSMEM);
    cudaFuncSetAttribute(gemm_cat<256, false, false>, cudaFuncAttributeMaxDynamicSharedMemorySize, GSMEM);

    cudaStream_t s1, s2;
    cudaStreamCreateWithFlags(&s1, cudaStreamNonBlocking);
    cudaStreamCreateWithFlags(&s2, cudaStreamNonBlocking);

    cudaEvent_t evRoot, evX, evW, evA0[3], evG0[3];
    cudaEventCreateWithFlags(&evRoot, cudaEventDisableTiming);
    cudaEventCreateWithFlags(&evX, cudaEventDisableTiming);
    cudaEventCreateWithFlags(&evW, cudaEventDisableTiming);
    for (int i = 0; i < 3; i++) {
        cudaEventCreateWithFlags(&evA0[i], cudaEventDisableTiming);
        cudaEventCreateWithFlags(&evG0[i], cudaEventDisableTiming);
    }

    dim3 ggH0(HALF0 / 128, 2);
    dim3 ggH1((NN - HALF0 + 127) / 128, 2);
    auto aggBlocks = [](int nodes) { return (nodes * 32 + 255) / 256; };
    int nEdgeQuads = (E + 1023) / 1024;

    cudaEventRecord(evRoot, 0);
    cudaStreamWaitEvent(s1, evRoot, 0);
    cudaStreamWaitEvent(s2, evRoot, 0);

    // ---- s1: conversions ----
    conv_x_kernel<<<(NN * 128 + 255) / 256, 256, 0, s1>>>(x);
    cudaEventRecord(evX, s1);
    conv_w_all_kernel<<<(W0_ELEMS + 2 * W12_ELEMS + 255) / 256, 256, 0, s1>>>(
        Wl0, Wr0, Wl1, Wr1, Wl2, Wr2, Bf);
    cudaEventRecord(evW, s1);

    // ---- main: CSR build ----
    zero_counts_kernel<<<(NN + 255) / 256, 256>>>();
    hist_kernel<<<nEdgeQuads, 256>>>(dst, E);
    scan_fused_kernel<<<NSCAN, 256>>>();
    scatter_kernel<<<nEdgeQuads, 256>>>(src, dst, E);

    // =========== layer 0 ===========
    cudaStreamWaitEvent(0, evX, 0);
    agg_f16<false><<<aggBlocks(HALF0), 256>>>(Xh, Mh, 0, HALF0);
    cudaEventRecord(evA0[0], 0);
    agg_f16<false><<<aggBlocks(NN - HALF0), 256>>>(Xh, Mh, HALF0, NN);

    cudaStreamWaitEvent(s2, evA0[0], 0);
    cudaStreamWaitEvent(s2, evW, 0);
    gemm_cat<128, true, true><<<ggH0, 256, GSMEM, s2>>>(
        Mh, Xh, Bf0, bl0, g0, b0, rm0, rv0, nullptr, h1h, 0, NN);
    cudaEventRecord(evG0[0], s2);

    cudaStreamWaitEvent(0, evW, 0);
    gemm_cat<128, true, true><<<ggH1, 256, GSMEM>>>(
        Mh, Xh, Bf0, bl0, g0, b0, rm0, rv0, nullptr, h1h, HALF0, NN);
    cudaStreamWaitEvent(0, evG0[0], 0);

    // =========== layer 1 ===========
    agg_f16<true><<<aggBlocks(HALF0), 256>>>(h1h, Mh, 0, HALF0);
    cudaEventRecord(evA0[1], 0);
    agg_f16<true><<<aggBlocks(NN - HALF0), 256>>>(h1h, Mh, HALF0, NN);

    cudaStreamWaitEvent(s2, evA0[1], 0);
    gemm_cat<256, true, true><<<ggH0, 256, GSMEM, s2>>>(
        Mh, h1h, Bf1, bl1, g1, b1, rm1, rv1, nullptr, h2h, 0, NN);
    cudaEventRecord(evG0[1], s2);

    gemm_cat<256, true, true><<<ggH1, 256, GSMEM>>>(
        Mh, h1h, Bf1, bl1, g1, b1, rm1, rv1, nullptr, h2h, HALF0, NN);
    cudaStreamWaitEvent(0, evG0[1], 0);

    // =========== layer 2 ===========
    agg_f16<true><<<aggBlocks(HALF0), 256>>>(h2h, Mh, 0, HALF0);
    cudaEventRecord(evA0[2], 0);
    agg_f16<true><<<aggBlocks(NN - HALF0), 256>>>(h2h, Mh, HALF0, NN);

    cudaStreamWaitEvent(s2, evA0[2], 0);
    gemm_cat<256, false, false><<<ggH0, 256, GSMEM, s2>>>(
        Mh, h2h, Bf2, bl2, g2, b2, rm2, rv2, (float*)d_out, nullptr, 0, NN);
    cudaEventRecord(evG0[2], s2);

    gemm_cat<256, false, false><<<ggH1, 256, GSMEM>>>(
        Mh, h2h, Bf2, bl2, g2, b2, rm2, rv2, (float*)d_out, nullptr, HALF0, NN);
    cudaStreamWaitEvent(0, evG0[2], 0);

    cudaEventDestroy(evRoot);
    cudaEventDestroy(evX);
    cudaEventDestroy(evW);
    for (int i = 0; i < 3; i++) {
        cudaEventDestroy(evA0[i]);
        cudaEventDestroy(evG0[i]);
    }
    cudaStreamDestroy(s1);
    cudaStreamDestroy(s2);
}

// round 16
// speedup vs baseline: 1.1847x; 1.0001x over previous
#include <cuda_runtime.h>
#include <cuda_fp16.h>
#include <cstdint>

#define NN 50000
#define EMAX 800000
#define EPS 1e-5f
#define HALF0 25088   // 196 * 128
#define NSCAN 196     // ceil(NN/256)

__device__ __forceinline__ void cpasync16(uint32_t dst, const void* src) {
    asm volatile("cp.async.cg.shared.global [%0], [%1], 16;" :: "r"(dst), "l"(src));
}
__device__ __forceinline__ void cpasync16z(uint32_t dst, const void* src, int size) {
    asm volatile("cp.async.cg.shared.global [%0], [%1], 16, %2;" :: "r"(dst), "l"(src), "r"(size));
}
__device__ __forceinline__ void cpcommit() { asm volatile("cp.async.commit_group;" ::: "memory"); }
__device__ __forceinline__ void cpwait0() { asm volatile("cp.async.wait_group 0;" ::: "memory"); }
__device__ __forceinline__ void cpwait1() { asm volatile("cp.async.wait_group 1;" ::: "memory"); }
__device__ __forceinline__ void cpwait2() { asm volatile("cp.async.wait_group 2;" ::: "memory"); }

// ======================= scratch =======================
__device__ __half g_Xh[NN * 128];
__device__ __half g_h1h[NN * 256];
__device__ __half g_h2h[NN * 256];
__device__ __half g_Mh[NN * 256];
__device__ __align__(16) __half g_Bf[256 * 256 + 2 * 256 * 512];
__device__ int g_counts[NN];
__device__ int g_offsets[NN + 1];
__device__ int g_cursor[NN];
__device__ int g_esrc[EMAX];
__device__ int g_bsum[NSCAN];
__device__ int g_flag[NSCAN];

// ======================= CSR build =======================
__global__ void zero_counts_kernel() {
    int i = blockIdx.x * blockDim.x + threadIdx.x;
    if (i < NN) g_counts[i] = 0;
    if (i < NSCAN) g_flag[i] = 0;
}
// hist: 8 edges per thread via 2x int4
__global__ void hist_kernel(const int* __restrict__ dst, int E) {
    int q = blockIdx.x * blockDim.x + threadIdx.x;
    int e = q * 8;
    if (e + 8 <= E) {
        int4 d0 = *(const int4*)(dst + e);
        int4 d1 = *(const int4*)(dst + e + 4);
        atomicAdd(&g_counts[d0.x], 1);
        atomicAdd(&g_counts[d0.y], 1);
        atomicAdd(&g_counts[d0.z], 1);
        atomicAdd(&g_counts[d0.w], 1);
        atomicAdd(&g_counts[d1.x], 1);
        atomicAdd(&g_counts[d1.y], 1);
        atomicAdd(&g_counts[d1.z], 1);
        atomicAdd(&g_counts[d1.w], 1);
    } else {
        for (int k = e; k < E; k++) atomicAdd(&g_counts[dst[k]], 1);
    }
}
__global__ void scan_fused_kernel() {
    __shared__ int s[256];
    __shared__ int sp[256];
    int tid = threadIdx.x;
    int i = blockIdx.x * 256 + tid;
    int v = (i < NN) ? g_counts[i] : 0;
    s[tid] = v;
    __syncthreads();
    #pragma unroll
    for (int off = 1; off < 256; off <<= 1) {
        int t = (tid >= off) ? s[tid - off] : 0;
        __syncthreads();
        s[tid] += t;
        __syncthreads();
    }
    if (tid == 255) {
        g_bsum[blockIdx.x] = s[255];
        __threadfence();
        atomicExch(&g_flag[blockIdx.x], 1);
    }
    int pre = 0;
    for (int b = tid; b < blockIdx.x; b += 256) {
        while (atomicAdd(&g_flag[b], 0) == 0) { }
        pre += g_bsum[b];
    }
    sp[tid] = pre;
    __syncthreads();
    #pragma unroll
    for (int off = 128; off > 0; off >>= 1) {
        if (tid < off) sp[tid] += sp[tid + off];
        __syncthreads();
    }
    int base = sp[0];
    if (i < NN) {
        g_offsets[i] = base + s[tid] - v;
        g_cursor[i] = 0;
    }
    if (blockIdx.x == NSCAN - 1 && tid == 255) g_offsets[NN] = base + s[255];
}
// scatter: 8 edges per thread via 2x int4
__global__ void scatter_kernel(const int* __restrict__ src, const int* __restrict__ dst, int E) {
    int q = blockIdx.x * blockDim.x + threadIdx.x;
    int e = q * 8;
    if (e + 8 <= E) {
        int4 d0 = *(const int4*)(dst + e);
        int4 d1 = *(const int4*)(dst + e + 4);
        int4 s0 = *(const int4*)(src + e);
        int4 s1 = *(const int4*)(src + e + 4);
        int p;
        p = atomicAdd(&g_cursor[d0.x], 1); g_esrc[g_offsets[d0.x] + p] = s0.x;
        p = atomicAdd(&g_cursor[d0.y], 1); g_esrc[g_offsets[d0.y] + p] = s0.y;
        p = atomicAdd(&g_cursor[d0.z], 1); g_esrc[g_offsets[d0.z] + p] = s0.z;
        p = atomicAdd(&g_cursor[d0.w], 1); g_esrc[g_offsets[d0.w] + p] = s0.w;
        p = atomicAdd(&g_cursor[d1.x], 1); g_esrc[g_offsets[d1.x] + p] = s1.x;
        p = atomicAdd(&g_cursor[d1.y], 1); g_esrc[g_offsets[d1.y] + p] = s1.y;
        p = atomicAdd(&g_cursor[d1.z], 1); g_esrc[g_offsets[d1.z] + p] = s1.z;
        p = atomicAdd(&g_cursor[d1.w], 1); g_esrc[g_offsets[d1.w] + p] = s1.w;
    } else {
        for (int k = e; k < E; k++) {
            int d = dst[k];
            int p = atomicAdd(&g_cursor[d], 1);
            g_esrc[g_offsets[d] + p] = src[k];
        }
    }
}

// ======================= conversion =======================
__global__ void conv_x_kernel(const float* __restrict__ x) {
    int i = blockIdx.x * blockDim.x + threadIdx.x;
    if (i < NN * 128) g_Xh[i] = __float2half(x[i]);
}
#define W0_ELEMS (256 * 256)
#define W12_ELEMS (256 * 512)
__global__ void conv_w_all_kernel(const float* __restrict__ Wl0, const float* __restrict__ Wr0,
                                  const float* __restrict__ Wl1, const float* __restrict__ Wr1,
                                  const float* __restrict__ Wl2, const float* __restrict__ Wr2,
                                  __half* __restrict__ Bf) {
    int i = blockIdx.x * blockDim.x + threadIdx.x;
    int tot = W0_ELEMS + 2 * W12_ELEMS;
    if (i >= tot) return;
    const float *Wl, *Wr;
    int r, K;
    if (i < W0_ELEMS) { Wl = Wl0; Wr = Wr0; K = 128; r = i; }
    else if (i < W0_ELEMS + W12_ELEMS) { Wl = Wl1; Wr = Wr1; K = 256; r = i - W0_ELEMS; }
    else { Wl = Wl2; Wr = Wr2; K = 256; r = i - W0_ELEMS - W12_ELEMS; }
    int n = r / (2 * K);
    int k = r - n * 2 * K;
    float f = (k < K) ? Wl[k * 256 + n] : Wr[(k - K) * 256 + n];
    g_Bf[i] = __float2half(f);
}

// ======================= mean aggregation: one warp per node, unroll x8 + idx prefetch ====
template <bool WIDE>
__global__ __launch_bounds__(256) void agg_f16(const __half* __restrict__ h,
                                               __half* __restrict__ mean,
                                               int nodeBeg, int nodeEnd) {
    int w = (blockIdx.x * blockDim.x + threadIdx.x) >> 5;
    int node = nodeBeg + w;
    if (node >= nodeEnd) return;
    int lane = threadIdx.x & 31;
    int beg = g_offsets[node], end = g_offsets[node + 1];

    if (WIDE) {
        const uint4* base = reinterpret_cast<const uint4*>(h) + lane;
        float a0 = 0.f, a1 = 0.f, a2 = 0.f, a3 = 0.f, a4 = 0.f, a5 = 0.f, a6 = 0.f, a7 = 0.f;
        int e = beg;
        int sidx[8];
        bool have = (e + 8 <= end);
        if (have) {
            #pragma unroll
            for (int j = 0; j < 8; j++) sidx[j] = g_esrc[e + j];
        }
        while (have) {
            uint4 t[8];
            #pragma unroll
            for (int j = 0; j < 8; j++) t[j] = __ldg(base + (size_t)sidx[j] * 32);
            e += 8;
            have = (e + 8 <= end);
            if (have) {
                #pragma unroll
                for (int j = 0; j < 8; j++) sidx[j] = g_esrc[e + j];
            }
            #pragma unroll
            for (int j = 0; j < 8; j++) {
                float2 f;
                f = __half22float2(*(const __half2*)&t[j].x); a0 += f.x; a1 += f.y;
                f = __half22float2(*(const __half2*)&t[j].y); a2 += f.x; a3 += f.y;
                f = __half22float2(*(const __half2*)&t[j].z); a4 += f.x; a5 += f.y;
                f = __half22float2(*(const __half2*)&t[j].w); a6 += f.x; a7 += f.y;
            }
        }
        for (; e < end; e++) {
            int s = g_esrc[e];
            uint4 t = __ldg(base + (size_t)s * 32);
            float2 f;
            f = __half22float2(*(const __half2*)&t.x); a0 += f.x; a1 += f.y;
            f = __half22float2(*(const __half2*)&t.y); a2 += f.x; a3 += f.y;
            f = __half22float2(*(const __half2*)&t.z); a4 += f.x; a5 += f.y;
            f = __half22float2(*(const __half2*)&t.w); a6 += f.x; a7 += f.y;
        }
        int deg = end - beg;
        float inv = 1.0f / (float)(deg > 1 ? deg : 1);
        __half2 p0 = __floats2half2_rn(a0 * inv, a1 * inv);
        __half2 p1 = __floats2half2_rn(a2 * inv, a3 * inv);
        __half2 p2 = __floats2half2_rn(a4 * inv, a5 * inv);
        __half2 p3 = __floats2half2_rn(a6 * inv, a7 * inv);
        uint4 o;
        o.x = *(uint32_t*)&p0; o.y = *(uint32_t*)&p1;
        o.z = *(uint32_t*)&p2; o.w = *(uint32_t*)&p3;
        reinterpret_cast<uint4*>(mean)[(size_t)node * 32 + lane] = o;
    } else {
        const uint2* base = reinterpret_cast<const uint2*>(h) + lane;
        float a0 = 0.f, a1 = 0.f, a2 = 0.f, a3 = 0.f;
        int e = beg;
        int sidx[8];
        bool have = (e + 8 <= end);
        if (have) {
            #pragma unroll
            for (int j = 0; j < 8; j++) sidx[j] = g_esrc[e + j];
        }
        while (have) {
            uint2 t[8];
            #pragma unroll
            for (int j = 0; j < 8; j++) t[j] = __ldg(base + (size_t)sidx[j] * 32);
            e += 8;
            have = (e + 8 <= end);
            if (have) {
                #pragma unroll
                for (int j = 0; j < 8; j++) sidx[j] = g_esrc[e + j];
            }
            #pragma unroll
            for (int j = 0; j < 8; j++) {
                float2 f;
                f = __half22float2(*(const __half2*)&t[j].x); a0 += f.x; a1 += f.y;
                f = __half22float2(*(const __half2*)&t[j].y); a2 += f.x; a3 += f.y;
            }
        }
        for (; e < end; e++) {
            int s = g_esrc[e];
            uint2 t = __ldg(base + (size_t)s * 32);
            float2 f;
            f = __half22float2(*(const __half2*)&t.x); a0 += f.x; a1 += f.y;
            f = __half22float2(*(const __half2*)&t.y); a2 += f.x; a3 += f.y;
        }
        int deg = end - beg;
        float inv = 1.0f / (float)(deg > 1 ? deg : 1);
        __half2 p0 = __floats2half2_rn(a0 * inv, a1 * inv);
        __half2 p1 = __floats2half2_rn(a2 * inv, a3 * inv);
        uint2 o;
        o.x = *(uint32_t*)&p0; o.y = *(uint32_t*)&p1;
        reinterpret_cast<uint2*>(mean)[(size_t)node * 32 + lane] = o;
    }
}

// ======================= fp16 mma.sync helper =======================
__device__ __forceinline__ void mma16816(float* c, const uint32_t* a, uint32_t b0, uint32_t b1) {
    asm("mma.sync.aligned.m16n8k16.row.col.f32.f16.f16.f32 "
        "{%0,%1,%2,%3}, {%4,%5,%6,%7}, {%8,%9}, {%0,%1,%2,%3};"
        : "+f"(c[0]), "+f"(c[1]), "+f"(c[2]), "+f"(c[3])
        : "r"(a[0]), "r"(a[1]), "r"(a[2]), "r"(a[3]), "r"(b0), "r"(b1));
}

// ======================= concat dual-source 3-stage GEMM =======================
#define SST 40
#define PLANE_B (128 * SST * 2)
#define BUF_B   (2 * PLANE_B)
#define NSTAGE  3
#define GSMEM   (NSTAGE * BUF_B)

template <int KH, bool PACK_OUT, bool RELU>
__global__ __launch_bounds__(256, 2) void gemm_cat(
    const __half* __restrict__ A1, const __half* __restrict__ A2,
    const __half* __restrict__ Bf,
    const float* __restrict__ blv, const float* __restrict__ gam,
    const float* __restrict__ bet, const float* __restrict__ rm,
    const float* __restrict__ rv,
    float* __restrict__ outf, __half* __restrict__ outh, int rowOff, int M)
{
    extern __shared__ __align__(16) char dsm[];
    constexpr int NC = 2 * KH / 32;
    constexpr int NC1 = KH / 32;

    int tid = threadIdx.x;
    int lane = tid & 31;
    int wid = tid >> 5;
    int g = lane >> 2;
    int tig = lane & 3;
    int wm = wid & 3;
    int wn = wid >> 2;
    int mBase = rowOff + blockIdx.x * 128;
    int nBase = blockIdx.y * 128;

    float acc[2][8][4];
    #pragma unroll
    for (int mt = 0; mt < 2; mt++)
        #pragma unroll
        for (int nt = 0; nt < 8; nt++)
            #pragma unroll
            for (int q = 0; q < 4; q++) acc[mt][nt][q] = 0.f;

    auto stageAB = [&](int kc, int buf) {
        char* base = dsm + buf * BUF_B;
        uint32_t dA = (uint32_t)__cvta_generic_to_shared(base);
        uint32_t dB = (uint32_t)__cvta_generic_to_shared(base + PLANE_B);
        const __half* Asrc = (kc < NC1) ? A1 : A2;
        int kOff = (kc < NC1) ? kc * 32 : (kc - NC1) * 32;
        #pragma unroll
        for (int i = 0; i < 2; i++) {
            int lin = tid + i * 256;
            int row = lin >> 2;
            int c8 = lin & 3;
            uint32_t doff = (uint32_t)(row * (SST * 2) + c8 * 16);
            int grow = mBase + row;
            int ok = (grow < M);
            int gr = ok ? grow : (M - 1);
            cpasync16z(dA + doff, Asrc + (size_t)gr * KH + kOff + c8 * 8, ok ? 16 : 0);
            cpasync16(dB + doff, Bf + (size_t)(nBase + row) * (2 * KH) + kc * 32 + c8 * 8);
        }
        cpcommit();
    };

    stageAB(0, 0);
    stageAB(1, 1);

    for (int kc = 0; kc < NC; kc++) {
        if (kc + 2 < NC) stageAB(kc + 2, (kc + 2) % NSTAGE);
        int rem = NC - 1 - kc;
        if (rem >= 2) cpwait2();
        else if (rem == 1) cpwait1();
        else cpwait0();
        __syncthreads();
        {
            char* base = dsm + (kc % NSTAGE) * BUF_B;
            const __half* sA = (const __half*)base;
            const __half* sB = (const __half*)(base + PLANE_B);
            #pragma unroll
            for (int ks = 0; ks < 2; ks++) {
                int k0 = ks * 16;
                uint32_t ah[2][4];
                #pragma unroll
                for (int mt = 0; mt < 2; mt++) {
                    int r0 = (wm * 32 + mt * 16 + g) * SST + k0 + 2 * tig;
                    ah[mt][0] = *(const uint32_t*)&sA[r0];
                    ah[mt][1] = *(const uint32_t*)&sA[r0 + 8 * SST];
                    ah[mt][2] = *(const uint32_t*)&sA[r0 + 8];
                    ah[mt][3] = *(const uint32_t*)&sA[r0 + 8 * SST + 8];
                }
                #pragma unroll
                for (int nt = 0; nt < 8; nt++) {
                    int b0 = (wn * 64 + nt * 8 + g) * SST + k0 + 2 * tig;
                    uint32_t bv0 = *(const uint32_t*)&sB[b0];
                    uint32_t bv1 = *(const uint32_t*)&sB[b0 + 8];
                    #pragma unroll
                    for (int mt = 0; mt < 2; mt++)
                        mma16816(acc[mt][nt], ah[mt], bv0, bv1);
                }
            }
        }
        __syncthreads();
    }

    #pragma unroll
    for (int nt = 0; nt < 8; nt++) {
        int c0 = nBase + wn * 64 + nt * 8 + 2 * tig;
        int c1 = c0 + 1;
        float sc0 = gam[c0] * rsqrtf(rv[c0] + EPS);
        float sh0 = (blv[c0] - rm[c0]) * sc0 + bet[c0];
        float sc1 = gam[c1] * rsqrtf(rv[c1] + EPS);
        float sh1 = (blv[c1] - rm[c1]) * sc1 + bet[c1];
        #pragma unroll
        for (int mt = 0; mt < 2; mt++) {
            int r0 = mBase + wm * 32 + mt * 16 + g;
            int r1 = r0 + 8;
            if (r0 < M) {
                float v00 = acc[mt][nt][0] * sc0 + sh0;
                float v01 = acc[mt][nt][1] * sc1 + sh1;
                if (RELU) { v00 = fmaxf(v00, 0.f); v01 = fmaxf(v01, 0.f); }
                if (PACK_OUT) {
                    __half2 hv = __floats2half2_rn(v00, v01);
                    *(__half2*)(outh + (size_t)r0 * 256 + c0) = hv;
                } else {
                    *(float2*)(outf + (size_t)r0 * 256 + c0) = make_float2(v00, v01);
                }
            }
            if (r1 < M) {
                float v10 = acc[mt][nt][2] * sc0 + sh0;
                float v11 = acc[mt][nt][3] * sc1 + sh1;
                if (RELU) { v10 = fmaxf(v10, 0.f); v11 = fmaxf(v11, 0.f); }
                if (PACK_OUT) {
                    __half2 hv = __floats2half2_rn(v10, v11);
                    *(__half2*)(outh + (size_t)r1 * 256 + c0) = hv;
                } else {
                    *(float2*)(outf + (size_t)r1 * 256 + c0) = make_float2(v10, v11);
                }
            }
        }
    }
}

// ======================= launch =======================
extern "C" void kernel_launch(void* const* d_in, const int* in_sizes, int n_in,
                              void* d_out, int out_size) {
    const float* x = (const float*)d_in[0];
    const int* ei = (const int*)d_in[1];
    int E = in_sizes[1] / 2;
    const int* src = ei;
    const int* dst = ei + E;

    const float* Wl0 = (const float*)d_in[2];
    const float* bl0 = (const float*)d_in[3];
    const float* Wr0 = (const float*)d_in[4];
    const float* g0 = (const float*)d_in[5];
    const float* b0 = (const float*)d_in[6];
    const float* rm0 = (const float*)d_in[7];
    const float* rv0 = (const float*)d_in[8];
    const float* Wl1 = (const float*)d_in[9];
    const float* bl1 = (const float*)d_in[10];
    const float* Wr1 = (const float*)d_in[11];
    const float* g1 = (const float*)d_in[12];
    const float* b1 = (const float*)d_in[13];
    const float* rm1 = (const float*)d_in[14];
    const float* rv1 = (const float*)d_in[15];
    const float* Wl2 = (const float*)d_in[16];
    const float* bl2 = (const float*)d_in[17];
    const float* Wr2 = (const float*)d_in[18];
    const float* g2 = (const float*)d_in[19];
    const float* b2 = (const float*)d_in[20];
    const float* rm2 = (const float*)d_in[21];
    const float* rv2 = (const float*)d_in[22];

    __half *Xh, *h1h, *h2h, *Mh, *Bf;
    cudaGetSymbolAddress((void**)&Xh, g_Xh);
    cudaGetSymbolAddress((void**)&h1h, g_h1h);
    cudaGetSymbolAddress((void**)&h2h, g_h2h);
    cudaGetSymbolAddress((void**)&Mh, g_Mh);
    cudaGetSymbolAddress((void**)&Bf, g_Bf);
    __half* Bf0 = Bf;
    __half* Bf1 = Bf0 + 256 * 256;
    __half* Bf2 = Bf1 + 256 * 512;

    cudaFuncSetAttribute(gemm_cat<128, true, true>, cudaFuncAttributeMaxDynamicSharedMemorySize, GSMEM);
    cudaFuncSetAttribute(gemm_cat<256, true, true>, cudaFuncAttributeMaxDynamicSharedMemorySize, GSMEM);
    cudaFuncSetAttribute(gemm_cat<256, false, false>, cudaFuncAttributeMaxDynamicSharedMemorySize, GSMEM);

    cudaStream_t s1, s2;
    cudaStreamCreateWithFlags(&s1, cudaStreamNonBlocking);
    cudaStreamCreateWithFlags(&s2, cudaStreamNonBlocking);

    cudaEvent_t evRoot, evX, evW, evA0[3], evG0[3];
    cudaEventCreateWithFlags(&evRoot, cudaEventDisableTiming);
    cudaEventCreateWithFlags(&evX, cudaEventDisableTiming);
    cudaEventCreateWithFlags(&evW, cudaEventDisableTiming);
    for (int i = 0; i < 3; i++) {
        cudaEventCreateWithFlags(&evA0[i], cudaEventDisableTiming);
        cudaEventCreateWithFlags(&evG0[i], cudaEventDisableTiming);
    }

    dim3 ggH0(HALF0 / 128, 2);
    dim3 ggH1((NN - HALF0 + 127) / 128, 2);
    auto aggBlocks = [](int nodes) { return (nodes * 32 + 255) / 256; };
    int nEdgeOcts = (E + 2047) / 2048;   // 8 edges/thread, 256 threads

    cudaEventRecord(evRoot, 0);
    cudaStreamWaitEvent(s1, evRoot, 0);
    cudaStreamWaitEvent(s2, evRoot, 0);

    // ---- s1: conversions ----
    conv_x_kernel<<<(NN * 128 + 255) / 256, 256, 0, s1>>>(x);
    cudaEventRecord(evX, s1);
    conv_w_all_kernel<<<(W0_ELEMS + 2 * W12_ELEMS + 255) / 256, 256, 0, s1>>>(
        Wl0, Wr0, Wl1, Wr1, Wl2, Wr2, Bf);
    cudaEventRecord(evW, s1);

    // ---- main: CSR build ----
    zero_counts_kernel<<<(NN + 255) / 256, 256>>>();
    hist_kernel<<<nEdgeOcts, 256>>>(dst, E);
    scan_fused_kernel<<<NSCAN, 256>>>();
    scatter_kernel<<<nEdgeOcts, 256>>>(src, dst, E);

    // =========== layer 0 ===========
    cudaStreamWaitEvent(0, evX, 0);
    agg_f16<false><<<aggBlocks(HALF0), 256>>>(Xh, Mh, 0, HALF0);
    cudaEventRecord(evA0[0], 0);
    agg_f16<false><<<aggBlocks(NN - HALF0), 256>>>(Xh, Mh, HALF0, NN);

    cudaStreamWaitEvent(s2, evA0[0], 0);
    cudaStreamWaitEvent(s2, evW, 0);
    gemm_cat<128, true, true><<<ggH0, 256, GSMEM, s2>>>(
        Mh, Xh, Bf0, bl0, g0, b0, rm0, rv0, nullptr, h1h, 0, NN);
    cudaEventRecord(evG0[0], s2);

    cudaStreamWaitEvent(0, evW, 0);
    gemm_cat<128, true, true><<<ggH1, 256, GSMEM>>>(
        Mh, Xh, Bf0, bl0, g0, b0, rm0, rv0, nullptr, h1h, HALF0, NN);
    cudaStreamWaitEvent(0, evG0[0], 0);

    // =========== layer 1 ===========
    agg_f16<true><<<aggBlocks(HALF0), 256>>>(h1h, Mh, 0, HALF0);
    cudaEventRecord(evA0[1], 0);
    agg_f16<true><<<aggBlocks(NN - HALF0), 256>>>(h1h, Mh, HALF0, NN);

    cudaStreamWaitEvent(s2, evA0[1], 0);
    gemm_cat<256, true, true><<<ggH0, 256, GSMEM, s2>>>(
        Mh, h1h, Bf1, bl1, g1, b1, rm1, rv1, nullptr, h2h, 0, NN);
    cudaEventRecord(evG0[1], s2);

    gemm_cat<256, true, true><<<ggH1, 256, GSMEM>>>(
        Mh, h1h, Bf1, bl1, g1, b1, rm1, rv1, nullptr, h2h, HALF0, NN);
    cudaStreamWaitEvent(0, evG0[1], 0);

    // =========== layer 2 ===========
    agg_f16<true><<<aggBlocks(HALF0), 256>>>(h2h, Mh, 0, HALF0);
    cudaEventRecord(evA0[2], 0);
    agg_f16<true><<<aggBlocks(NN - HALF0), 256>>>(h2h, Mh, HALF0, NN);

    cudaStreamWaitEvent(s2, evA0[2], 0);
    gemm_cat<256, false, false><<<ggH0, 256, GSMEM, s2>>>(
        Mh, h2h, Bf2, bl2, g2, b2, rm2, rv2, (float*)d_out, nullptr, 0, NN);
    cudaEventRecord(evG0[2], s2);

    gemm_cat<256, false, false><<<ggH1, 256, GSMEM>>>(
        Mh, h2h, Bf2, bl2, g2, b2, rm2, rv2, (float*)d_out, nullptr, HALF0, NN);
    cudaStreamWaitEvent(0, evG0[2], 0);

    cudaEventDestroy(evRoot);
    cudaEventDestroy(evX);
    cudaEventDestroy(evW);
    for (int i = 0; i < 3; i++) {
        cudaEventDestroy(evA0[i]);
        cudaEventDestroy(evG0[i]);
    }
    cudaStreamDestroy(s1);
    cudaStreamDestroy(s2);
}